// round 8
// baseline (speedup 1.0000x reference)
#include <cuda_runtime.h>

// ScatterLoss — per-class contrastive hinge loss.
// d_in[0] = output [N, D] float32 (N=65536, D=512)
// d_in[1] = label_id [N] int32
// out     = scalar float32
//
// loss = (1/N) * sum_k cnt_k * relu(1 - || s_k/c_k - (T - s_k)/(N - c_k) + 1e-6 ||_2)^2

#define NCLS 512
#define DDIM 512
#define NF4  (DDIM / 4)   // 128 float4 columns
#define CAP  1024         // max rows per class (counts ~128±11)
#define NSPL 4            // class split factor for the streaming kernel
#define PAD  32           // ints per 128B line — atomic-target padding
#define SCTA 32           // scatter CTAs

// Zeroed each replay by one memset node (0 bits == 0.0f == 0).
struct ZeroBlk {
    int   cnt[NCLS * PAD];
    float d2[NCLS * PAD];
    unsigned int ticket;
};
static __device__ ZeroBlk g_z;

static __device__ int   g_idx[NCLS * CAP];
static __device__ float g_sumsp[NSPL][NCLS][DDIM];   // per-quarter class sums

// ---------------------------------------------------------------------------
// K1: two-phase counting-sort scatter. 32 CTAs x 512 threads, 4 labels each
// (one int4, kept in registers across phases).
//   P1: smem histogram (spread ATOMS).
//   P2: one global atomicAdd per (class, CTA) reserves a contiguous base
//       (16K atomics, 4 per padded counter line, vs 65K before).
//   P3: indices written at base + local position.
// ---------------------------------------------------------------------------
__global__ void __launch_bounds__(512) k_scatter(const int* __restrict__ lab, int N)
{
    __shared__ int scnt[NCLS];
    __shared__ int sbase[NCLS];
    __shared__ int scur[NCLS];

    int t = threadIdx.x;
    scnt[t] = 0; scur[t] = 0;           // blockDim == NCLS == 512
    __syncthreads();

    // this CTA's chunk: 2048 labels = 512 int4, one per thread
    int v4i = blockIdx.x * 512 + t;     // int4 index
    int4 v  = ((const int4*)lab)[v4i];
    int i0  = v4i * 4;                  // first row index of this int4

    if ((unsigned)v.x < NCLS) atomicAdd(&scnt[v.x], 1);
    if ((unsigned)v.y < NCLS) atomicAdd(&scnt[v.y], 1);
    if ((unsigned)v.z < NCLS) atomicAdd(&scnt[v.z], 1);
    if ((unsigned)v.w < NCLS) atomicAdd(&scnt[v.w], 1);
    __syncthreads();

    int c = scnt[t];
    if (c > 0) sbase[t] = atomicAdd(&g_z.cnt[t * PAD], c);
    __syncthreads();

    int k, p;
    k = v.x; if ((unsigned)k < NCLS) { p = sbase[k] + atomicAdd(&scur[k], 1); if (p < CAP) g_idx[k * CAP + p] = i0;     }
    k = v.y; if ((unsigned)k < NCLS) { p = sbase[k] + atomicAdd(&scur[k], 1); if (p < CAP) g_idx[k * CAP + p] = i0 + 1; }
    k = v.z; if ((unsigned)k < NCLS) { p = sbase[k] + atomicAdd(&scur[k], 1); if (p < CAP) g_idx[k * CAP + p] = i0 + 2; }
    k = v.w; if ((unsigned)k < NCLS) { p = sbase[k] + atomicAdd(&scur[k], 1); if (p < CAP) g_idx[k * CAP + p] = i0 + 3; }
}

// ---------------------------------------------------------------------------
// K2: per-class partial sums. Four CTAs per class (contiguous quarters of
// the row list). Index words load warp-uniform (broadcast); row data is read
// exactly once -> __ldcs streaming hint keeps L2 for metadata.
// Reads the full 128 MB matrix exactly once -> HBM bound (dominant kernel).
// ---------------------------------------------------------------------------
__global__ void __launch_bounds__(128) k_class_sum_q(const float* __restrict__ out)
{
    int k  = blockIdx.x >> 2;
    int h  = blockIdx.x & 3;
    int nk = min(g_z.cnt[k * PAD], CAP);
    int j0 = (h * nk) >> 2;
    int j1 = ((h + 1) * nk) >> 2;
    int nj = j1 - j0;

    const int* idx = g_idx + k * CAP + j0;
    int q = threadIdx.x;  // float4 column 0..127

    float4 acc = make_float4(0.f, 0.f, 0.f, 0.f);
    #pragma unroll 8
    for (int j = 0; j < nj; j++) {
        int r = __ldg(idx + j);
        const float4* row = (const float4*)(out + (size_t)r * DDIM);
        float4 v = __ldcs(row + q);          // read-once: evict-first
        acc.x += v.x; acc.y += v.y; acc.z += v.z; acc.w += v.w;
    }
    ((float4*)g_sumsp[h][k])[q] = acc;
}

// ---------------------------------------------------------------------------
// K3: fused grand-total + per-class d^2 partials + last-CTA finalize.
// 32 CTAs x 256 threads; CTA owns 4 float4-columns, thread owns 2 classes.
// Per thread: 32 L2-resident float4 loads, ONE d^2 atomicAdd per class
// (16K total, 4x fewer than before). Last CTA does hinge + weighted mean.
// ---------------------------------------------------------------------------
__global__ void __launch_bounds__(256) k_colloss(float* __restrict__ outp, float fN)
{
    __shared__ float4 red[256];
    __shared__ unsigned int s_tkt;
    int t   = threadIdx.x;
    int cg0 = blockIdx.x * 4;          // first float4 column of this CTA

    // fold the 4 quarter-sums for 2 classes x 4 columns
    float4 s[2][4];
    #pragma unroll
    for (int m = 0; m < 2; m++) {
        int k = t + m * 256;
        #pragma unroll
        for (int cc = 0; cc < 4; cc++) {
            float4 a = make_float4(0.f, 0.f, 0.f, 0.f);
            #pragma unroll
            for (int h = 0; h < NSPL; h++) {
                float4 v = ((const float4*)g_sumsp[h][k])[cg0 + cc];
                a.x += v.x; a.y += v.y; a.z += v.z; a.w += v.w;
            }
            s[m][cc] = a;
        }
    }

    // grand total T for the 4 columns (block tree-reduce over all classes)
    float4 T[4];
    #pragma unroll
    for (int cc = 0; cc < 4; cc++) {
        float4 x;
        x.x = s[0][cc].x + s[1][cc].x; x.y = s[0][cc].y + s[1][cc].y;
        x.z = s[0][cc].z + s[1][cc].z; x.w = s[0][cc].w + s[1][cc].w;
        red[t] = x;
        __syncthreads();
        #pragma unroll
        for (int sh = 128; sh > 0; sh >>= 1) {
            if (t < sh) {
                float4 b = red[t + sh];
                red[t].x += b.x; red[t].y += b.y; red[t].z += b.z; red[t].w += b.w;
            }
            __syncthreads();
        }
        T[cc] = red[0];
        __syncthreads();
    }

    // per-class d^2 contribution over this CTA's 16 dims -> one atomic each
    #pragma unroll
    for (int m = 0; m < 2; m++) {
        int k = t + m * 256;
        int c = g_z.cnt[k * PAD];
        if (c > 0) {
            float fc  = (float)c;
            float ip  = 1.f / fc;
            float in_ = 1.f / (fN - fc);
            float p = 0.f;
            #pragma unroll
            for (int cc = 0; cc < 4; cc++) {
                float dx = s[m][cc].x * ip - (T[cc].x - s[m][cc].x) * in_ + 1e-6f;
                float dy = s[m][cc].y * ip - (T[cc].y - s[m][cc].y) * in_ + 1e-6f;
                float dz = s[m][cc].z * ip - (T[cc].z - s[m][cc].z) * in_ + 1e-6f;
                float dw = s[m][cc].w * ip - (T[cc].w - s[m][cc].w) * in_ + 1e-6f;
                p += dx * dx + dy * dy + dz * dz + dw * dw;
            }
            atomicAdd(&g_z.d2[k * PAD], p);
        }
    }

    // last-CTA finalize
    __threadfence();
    __syncthreads();
    if (t == 0) s_tkt = atomicAdd(&g_z.ticket, 1u);
    __syncthreads();
    if (s_tkt == (unsigned)(gridDim.x - 1)) {
        float w = 0.f;
        #pragma unroll
        for (int m = 0; m < 2; m++) {
            int k = t + m * 256;
            int c = g_z.cnt[k * PAD];
            if (c > 0) {
                float dist = sqrtf(g_z.d2[k * PAD]);
                float mg = fmaxf(1.0f - dist, 0.f);   // MARGIN = 1.0
                w += (float)c * mg * mg;
            }
        }
        ((float*)red)[t] = w;
        __syncthreads();
        #pragma unroll
        for (int sh = 128; sh > 0; sh >>= 1) {
            if (t < sh) ((float*)red)[t] += ((float*)red)[t + sh];
            __syncthreads();
        }
        if (t == 0) outp[0] = ((float*)red)[0] / fN;
    }
}

// ---------------------------------------------------------------------------
extern "C" void kernel_launch(void* const* d_in, const int* in_sizes, int n_in,
                              void* d_out, int out_size)
{
    const float* output = (const float*)d_in[0];
    const int*   label  = (const int*)d_in[1];
    int N = in_sizes[1];

    void* zptr = nullptr;
    cudaGetSymbolAddress(&zptr, g_z);            // host-side query; capture-safe
    cudaMemsetAsync(zptr, 0, sizeof(ZeroBlk));   // counters + d2 + ticket

    k_scatter<<<SCTA, 512>>>(label, N);
    k_class_sum_q<<<NCLS * NSPL, 128>>>(output);
    k_colloss<<<NF4 / 4, 256>>>((float*)d_out, (float)N);
}